// round 1
// baseline (speedup 1.0000x reference)
#include <cuda_runtime.h>
#include <cstdint>

// Problem constants (fixed by the reference: B=4, S=4096, H=1024, C=256)
#define Hh 1024
#define Cc 256
#define ROWS_PER_TENSOR 16384   // 4*4096
#define ROWS_TOTAL      32768
#define BM 64                   // rows per block
#define KC 32                   // k-chunk
#define NTHREADS 256

__device__ float g_csq[Cc];

// --- Kernel 1: codebook squared norms (one block per code) -----------------
__global__ void csq_kernel(const float* __restrict__ cb) {
    const int c = blockIdx.x;
    const int t = threadIdx.x;          // 128 threads
    const float4* row = reinterpret_cast<const float4*>(cb + (size_t)c * Hh);
    float s = 0.f;
    for (int i = t; i < Hh / 4; i += 128) {
        float4 v = row[i];
        s += v.x * v.x + v.y * v.y + v.z * v.z + v.w * v.w;
    }
    #pragma unroll
    for (int o = 16; o > 0; o >>= 1) s += __shfl_xor_sync(0xffffffffu, s, o);
    __shared__ float ws[4];
    if ((t & 31) == 0) ws[t >> 5] = s;
    __syncthreads();
    if (t == 0) g_csq[c] = ws[0] + ws[1] + ws[2] + ws[3];
}

// --- Kernel 2: fused distance-GEMM + argmin + masked gather ----------------
// Block: 256 threads as 16x16 (tx = code group, ty = row group).
// Thread accumulates 4 rows x 16 codes (8 f32x2 code-pairs) in fp32 via FFMA2.
__global__ __launch_bounds__(NTHREADS, 2)
void vq_kernel(const float* __restrict__ keys,
               const float* __restrict__ values,
               const float* __restrict__ cb,
               float* __restrict__ out) {
    __shared__ __align__(16) float xs[BM][36];     // padded: rows 4 apart -> distinct banks
    __shared__ __align__(16) float cs[KC][Cc];     // transposed codebook chunk
    __shared__ int   idx_s[BM];
    __shared__ float csq_s[Cc];

    const int tid = threadIdx.x;
    const int tx  = tid & 15;     // 0..15 : code partition (codes 2*tx+32*j+{0,1})
    const int ty  = tid >> 4;     // 0..15 : row partition  (rows ty*4+{0..3})
    const int rowBase = blockIdx.x * BM;

    csq_s[tid] = g_csq[tid];      // 256 threads <-> 256 codes

    // Source tensor is uniform per block (16384 % 64 == 0)
    const float* src_base;
    int srcRowBase;
    if (rowBase < ROWS_PER_TENSOR) { src_base = keys;   srcRowBase = rowBase; }
    else                           { src_base = values; srcRowBase = rowBase - ROWS_PER_TENSOR; }

    unsigned long long acc[4][8];
    #pragma unroll
    for (int r = 0; r < 4; r++)
        #pragma unroll
        for (int j = 0; j < 8; j++) acc[r][j] = 0ull;

    for (int k0 = 0; k0 < Hh; k0 += KC) {
        __syncthreads();   // protect smem from previous chunk's readers

        // Load X chunk: 64 rows x 32 floats = 512 float4, 2 per thread.
        #pragma unroll
        for (int i = 0; i < 2; i++) {
            int li  = tid + i * NTHREADS;      // 0..511
            int row = li >> 3;                 // 8 float4 per row
            int v4  = li & 7;
            const float* src = src_base + (size_t)(srcRowBase + row) * Hh + k0 + v4 * 4;
            float4 v = *reinterpret_cast<const float4*>(src);
            *reinterpret_cast<float4*>(&xs[row][v4 * 4]) = v;
        }
        // Load C chunk transposed: thread t owns code t. STS banks = t%32 -> conflict-free.
        {
            const float* src = cb + (size_t)tid * Hh + k0;
            #pragma unroll
            for (int i = 0; i < 8; i++) {
                float4 v = *reinterpret_cast<const float4*>(src + i * 4);
                cs[i * 4 + 0][tid] = v.x;
                cs[i * 4 + 1][tid] = v.y;
                cs[i * 4 + 2][tid] = v.z;
                cs[i * 4 + 3][tid] = v.w;
            }
        }
        __syncthreads();

        #pragma unroll 8
        for (int k = 0; k < KC; k++) {
            unsigned long long xsp[4];
            #pragma unroll
            for (int r = 0; r < 4; r++) {
                unsigned int xv = __float_as_uint(xs[ty * 4 + r][k]);
                asm("mov.b64 %0, {%1, %1};" : "=l"(xsp[r]) : "r"(xv));
            }
            unsigned long long cp[8];
            #pragma unroll
            for (int j = 0; j < 8; j++)
                cp[j] = *reinterpret_cast<const unsigned long long*>(&cs[k][2 * tx + 32 * j]);
            #pragma unroll
            for (int r = 0; r < 4; r++)
                #pragma unroll
                for (int j = 0; j < 8; j++)
                    asm("fma.rn.f32x2 %0, %1, %2, %0;"
                        : "+l"(acc[r][j]) : "l"(xsp[r]), "l"(cp[j]));
        }
    }

    // Epilogue: score = c_sq - 2*dot ; per-row argmin with first-index tie-break.
    float bestv[4];
    int   besti[4];
    #pragma unroll
    for (int r = 0; r < 4; r++) { bestv[r] = __int_as_float(0x7f800000); besti[r] = 0x7fffffff; }

    #pragma unroll
    for (int r = 0; r < 4; r++) {
        #pragma unroll
        for (int j = 0; j < 8; j++) {
            unsigned int lo, hi;
            asm("mov.b64 {%0, %1}, %2;" : "=r"(lo), "=r"(hi) : "l"(acc[r][j]));
            float d0 = __uint_as_float(lo);
            float d1 = __uint_as_float(hi);
            int c0 = 2 * tx + 32 * j;
            int c1 = c0 + 1;
            float s0 = csq_s[c0] - 2.0f * d0;
            float s1 = csq_s[c1] - 2.0f * d1;
            if (s0 < bestv[r] || (s0 == bestv[r] && c0 < besti[r])) { bestv[r] = s0; besti[r] = c0; }
            if (s1 < bestv[r] || (s1 == bestv[r] && c1 < besti[r])) { bestv[r] = s1; besti[r] = c1; }
        }
    }
    // Reduce across the 16 tx lanes (xor 1..8 stays inside the 16-lane group).
    #pragma unroll
    for (int o = 1; o < 16; o <<= 1) {
        #pragma unroll
        for (int r = 0; r < 4; r++) {
            float ov = __shfl_xor_sync(0xffffffffu, bestv[r], o);
            int   oi = __shfl_xor_sync(0xffffffffu, besti[r], o);
            if (ov < bestv[r] || (ov == bestv[r] && oi < besti[r])) { bestv[r] = ov; besti[r] = oi; }
        }
    }
    if (tx == 0) {
        #pragma unroll
        for (int r = 0; r < 4; r++) idx_s[ty * 4 + r] = besti[r];
    }
    __syncthreads();

    // Fused masked gather writeback: 64 rows x 256 float4.
    for (int i = tid; i < BM * (Hh / 4); i += NTHREADS) {
        int row = i >> 8;          // Hh/4 = 256 float4 per row
        int v4  = i & 255;
        int ci  = idx_s[row];
        float4 v = *reinterpret_cast<const float4*>(cb + (size_t)ci * Hh + v4 * 4);
        float m = (csq_s[ci] > 0.01f) ? 1.0f : 0.0f;   // ||c|| > 0.1
        v.x *= m; v.y *= m; v.z *= m; v.w *= m;
        size_t gr = (size_t)(rowBase + row);
        *reinterpret_cast<float4*>(out + gr * Hh + (size_t)v4 * 4) = v;
    }
}

extern "C" void kernel_launch(void* const* d_in, const int* in_sizes, int n_in,
                              void* d_out, int out_size) {
    const float* keys     = (const float*)d_in[0];   // [4,4096,1024] f32
    const float* values   = (const float*)d_in[1];   // [4,4096,1024] f32
    const float* codebook = (const float*)d_in[2];   // [256,1024]    f32
    float* out = (float*)d_out;                      // keys_c then values_c

    csq_kernel<<<Cc, 128>>>(codebook);
    vq_kernel<<<ROWS_TOTAL / BM, NTHREADS>>>(keys, values, codebook, out);
}

// round 3
// speedup vs baseline: 2.8771x; 2.8771x over previous
#include <cuda_runtime.h>
#include <cuda_bf16.h>
#include <cstdint>

// Problem constants (fixed): B=4, S=4096, H=1024, C=256
#define Hh 1024
#define Cc 256
#define ROWS_PER_TENSOR 16384
#define ROWS_TOTAL      32768
#define BM 128
#define KC 64
#define NCHUNK 16
#define NT 512
#define MARGIN 0.05f

// __device__ scratch (no allocation allowed)
__device__ __nv_bfloat16 g_chi[Cc * Hh];
__device__ __nv_bfloat16 g_clo[Cc * Hh];
__device__ float g_csq[Cc];
__device__ int   g_nflag;
__device__ int   g_frow[ROWS_TOTAL];
__device__ int   g_fcnt[ROWS_TOTAL];
__device__ int   g_fcand[ROWS_TOTAL][8];

// ---------------- helpers ----------------
__device__ __forceinline__ uint32_t swz128(uint32_t off) {   // XOR bits[6:4] ^= bits[9:7]
    return off ^ ((off >> 3) & 0x70u);
}
__device__ __forceinline__ uint32_t smem_u32(const void* p) {
    uint32_t a;
    asm("{ .reg .u64 t; cvta.to.shared.u64 t, %1; cvt.u32.u64 %0, t; }" : "=r"(a) : "l"(p));
    return a;
}
__device__ __forceinline__ void cpa16(uint32_t dst, const void* src) {
    asm volatile("{ .reg .u64 g; cvta.to.global.u64 g, %1; "
                 "cp.async.cg.shared.global [%0], [g], 16; }"
                 :: "r"(dst), "l"(src) : "memory");
}
#define CP_COMMIT() asm volatile("cp.async.commit_group;" ::: "memory")
#define CP_WAIT0()  asm volatile("cp.async.wait_group 0;" ::: "memory")

__device__ __forceinline__ void ldsm4(uint32_t* r, uint32_t addr) {
    asm volatile("ldmatrix.sync.aligned.m8n8.x4.shared.b16 {%0,%1,%2,%3}, [%4];"
                 : "=r"(r[0]), "=r"(r[1]), "=r"(r[2]), "=r"(r[3]) : "r"(addr));
}
__device__ __forceinline__ void mma16816(float* d, const uint32_t* a, uint32_t b0, uint32_t b1) {
    asm volatile("mma.sync.aligned.m16n8k16.row.col.f32.bf16.bf16.f32 "
                 "{%0,%1,%2,%3}, {%4,%5,%6,%7}, {%8,%9}, {%0,%1,%2,%3};"
                 : "+f"(d[0]), "+f"(d[1]), "+f"(d[2]), "+f"(d[3])
                 : "r"(a[0]), "r"(a[1]), "r"(a[2]), "r"(a[3]), "r"(b0), "r"(b1));
}
// fp32 -> (bf16 hi via RNE, residual -> bf16 lo)
__device__ __forceinline__ void split4(const float4 v, uint32_t& h01, uint32_t& h23,
                                       uint32_t& l01, uint32_t& l23) {
    float x[4] = {v.x, v.y, v.z, v.w};
    uint32_t hb[4]; float lo[4];
#pragma unroll
    for (int i = 0; i < 4; i++) {
        uint32_t u = __float_as_uint(x[i]);
        uint32_t r = u + 0x7fffu + ((u >> 16) & 1u);
        hb[i] = r & 0xffff0000u;
        lo[i] = x[i] - __uint_as_float(hb[i]);
    }
    h01 = (hb[0] >> 16) | (hb[1] & 0xffff0000u);
    h23 = (hb[2] >> 16) | (hb[3] & 0xffff0000u);
    asm("cvt.rn.bf16x2.f32 %0, %1, %2;" : "=r"(l01) : "f"(lo[1]), "f"(lo[0]));
    asm("cvt.rn.bf16x2.f32 %0, %1, %2;" : "=r"(l23) : "f"(lo[3]), "f"(lo[2]));
}

// ---------------- Kernel 1: codebook split + norms + flag reset ------------
__global__ void prep_kernel(const float* __restrict__ cb) {
    const int c = blockIdx.x;
    const int t = threadIdx.x;                 // 256 threads, one float4 each
    if (c == 0 && t == 0) g_nflag = 0;
    float4 v = reinterpret_cast<const float4*>(cb + (size_t)c * Hh)[t];
    float s = v.x * v.x + v.y * v.y + v.z * v.z + v.w * v.w;
    uint32_t h01, h23, l01, l23;
    split4(v, h01, h23, l01, l23);
    reinterpret_cast<uint2*>(g_chi + (size_t)c * Hh)[t] = make_uint2(h01, h23);
    reinterpret_cast<uint2*>(g_clo + (size_t)c * Hh)[t] = make_uint2(l01, l23);
#pragma unroll
    for (int o = 16; o > 0; o >>= 1) s += __shfl_xor_sync(0xffffffffu, s, o);
    __shared__ float ws[8];
    if ((t & 31) == 0) ws[t >> 5] = s;
    __syncthreads();
    if (t == 0) {
        float tot = 0.f;
#pragma unroll
        for (int i = 0; i < 8; i++) tot += ws[i];
        g_csq[c] = tot;
    }
}

// ---------------- Kernel 2: mma.sync GEMM + argmin + gather ----------------
// smem: 2 stages x (Ahi 16K | Alo 16K | Bhi 32K | Blo 32K) + epilogue arrays
#define STG 98304
#define OFF_AHI(s) ((s) * STG + 0)
#define OFF_ALO(s) ((s) * STG + 16384)
#define OFF_BHI(s) ((s) * STG + 32768)
#define OFF_BLO(s) ((s) * STG + 65536)
#define OFF_CSQ  196608
#define OFF_BV   197632
#define OFF_BI   199680
#define OFF_RMIN 201728
#define OFF_IDX  202240
#define OFF_CNT  202752
#define OFF_CAND 203264
#define SMEM_TOTAL 207360

__global__ __launch_bounds__(NT, 1)
void vq_gemm(const float* __restrict__ keys, const float* __restrict__ values,
             const float* __restrict__ cb, float* __restrict__ out) {
    extern __shared__ __align__(1024) char smem[];
    const uint32_t sb = smem_u32(smem);
    const int tid  = threadIdx.x;
    const int lane = tid & 31;
    const int wid  = tid >> 5;
    const int wm   = wid >> 2;          // 0..3 (M)
    const int wn   = wid & 3;           // 0..3 (N)
    const int rowBase = blockIdx.x * BM;

    const float* src_base; int srcRow;
    if (rowBase < ROWS_PER_TENSOR) { src_base = keys;   srcRow = rowBase; }
    else                           { src_base = values; srcRow = rowBase - ROWS_PER_TENSOR; }

    if (tid < Cc) reinterpret_cast<float*>(smem + OFF_CSQ)[tid] = g_csq[tid];
    if (tid < BM) reinterpret_cast<int*>(smem + OFF_CNT)[tid] = 0;

    float acc[2][8][4];
#pragma unroll
    for (int a = 0; a < 2; a++)
#pragma unroll
        for (int b = 0; b < 8; b++)
#pragma unroll
            for (int k = 0; k < 4; k++) acc[a][b][k] = 0.f;

    // ---- loaders (inlined via lambdas) ----
    auto loadB = [&](int c, int s) {
#pragma unroll
        for (int i = 0; i < 4; i++) {
            int li = tid + i * NT;
            int row = li >> 3, u = li & 7;
            const __nv_bfloat16* gh = g_chi + (size_t)row * Hh + c * KC + u * 8;
            const __nv_bfloat16* gl = g_clo + (size_t)row * Hh + c * KC + u * 8;
            uint32_t off = swz128((uint32_t)(row * 128 + u * 16));
            cpa16(sb + OFF_BHI(s) + off, gh);
            cpa16(sb + OFF_BLO(s) + off, gl);
        }
    };
    auto loadA = [&](float4* pf, int c) {
#pragma unroll
        for (int i = 0; i < 4; i++) {
            int li = tid + i * NT;
            int row = li >> 4, u = li & 15;
            pf[i] = *reinterpret_cast<const float4*>(
                src_base + (size_t)(srcRow + row) * Hh + c * KC + u * 4);
        }
    };
    auto storeA = [&](const float4* pf, int s) {
#pragma unroll
        for (int i = 0; i < 4; i++) {
            int li = tid + i * NT;
            int row = li >> 4, u = li & 15;
            uint32_t h01, h23, l01, l23;
            split4(pf[i], h01, h23, l01, l23);
            uint32_t off = swz128((uint32_t)(row * 128 + u * 8));
            *reinterpret_cast<uint2*>(smem + OFF_AHI(s) + off) = make_uint2(h01, h23);
            *reinterpret_cast<uint2*>(smem + OFF_ALO(s) + off) = make_uint2(l01, l23);
        }
    };

    // per-lane ldmatrix address components
    const int aRowB = (wm * 32 + (lane & 15)) * 128;       // + mt*2048
    const int aColB = (lane >> 4) * 16;
    const int bRow  = wn * 64 + ((lane >> 4) << 3) + (lane & 7);  // + p*16
    const int bColB = ((lane >> 3) & 1) * 16;

    // prologue: chunk 0
    float4 pf[4];
    loadB(0, 0); CP_COMMIT();
    loadA(pf, 0);
    storeA(pf, 0);
    CP_WAIT0();
    __syncthreads();

    for (int c = 0; c < NCHUNK; c++) {
        const int s = c & 1;
        if (c + 1 < NCHUNK) { loadB(c + 1, s ^ 1); CP_COMMIT(); loadA(pf, c + 1); }

        const uint32_t aHi = sb + OFF_AHI(s), aLo = sb + OFF_ALO(s);
        const uint32_t bHi = sb + OFF_BHI(s), bLo = sb + OFF_BLO(s);
#pragma unroll
        for (int ks = 0; ks < 4; ks++) {
            uint32_t ah[2][4], al[2][4];
#pragma unroll
            for (int mt = 0; mt < 2; mt++) {
                uint32_t off = swz128((uint32_t)(aRowB + mt * 2048 + ks * 32 + aColB));
                ldsm4(ah[mt], aHi + off);
                ldsm4(al[mt], aLo + off);
            }
#pragma unroll
            for (int p = 0; p < 4; p++) {
                uint32_t boff = swz128((uint32_t)((bRow + p * 16) * 128 + ks * 32 + bColB));
                uint32_t bh[4], bl[4];
                ldsm4(bh, bHi + boff);
                ldsm4(bl, bLo + boff);
#pragma unroll
                for (int mt = 0; mt < 2; mt++) {
                    mma16816(acc[mt][2 * p],     ah[mt], bh[0], bh[1]);
                    mma16816(acc[mt][2 * p + 1], ah[mt], bh[2], bh[3]);
                    mma16816(acc[mt][2 * p],     ah[mt], bl[0], bl[1]);
                    mma16816(acc[mt][2 * p + 1], ah[mt], bl[2], bl[3]);
                    mma16816(acc[mt][2 * p],     al[mt], bh[0], bh[1]);
                    mma16816(acc[mt][2 * p + 1], al[mt], bh[2], bh[3]);
                }
            }
        }
        if (c + 1 < NCHUNK) { storeA(pf, s ^ 1); CP_WAIT0(); }
        __syncthreads();
    }

    // ---- epilogue: scores, per-row argmin, candidates, writeback ----
    const float* csq = reinterpret_cast<const float*>(smem + OFF_CSQ);
    float* bvs   = reinterpret_cast<float*>(smem + OFF_BV);
    int*   bis   = reinterpret_cast<int*>(smem + OFF_BI);
    float* rminv = reinterpret_cast<float*>(smem + OFF_RMIN);
    int*   idx_s = reinterpret_cast<int*>(smem + OFF_IDX);
    int*   cnt_s = reinterpret_cast<int*>(smem + OFF_CNT);
    int*   cand  = reinterpret_cast<int*>(smem + OFF_CAND);

    // slots: 0:(mt0,r) 1:(mt0,r+8) 2:(mt1,r) 3:(mt1,r+8)
    float mv[4]; int mi[4];
#pragma unroll
    for (int q = 0; q < 4; q++) { mv[q] = __int_as_float(0x7f800000); mi[q] = 0x7fffffff; }
#pragma unroll
    for (int mt = 0; mt < 2; mt++)
#pragma unroll
        for (int nt = 0; nt < 8; nt++) {
            int n0 = wn * 64 + nt * 8 + (lane & 3) * 2;
            float cq0 = csq[n0], cq1 = csq[n0 + 1];
            float s0 = cq0 - 2.f * acc[mt][nt][0];
            float s1 = cq1 - 2.f * acc[mt][nt][1];
            float s2 = cq0 - 2.f * acc[mt][nt][2];
            float s3 = cq1 - 2.f * acc[mt][nt][3];
            int q0 = mt * 2, q1 = mt * 2 + 1;
            if (s0 < mv[q0]) { mv[q0] = s0; mi[q0] = n0; }
            if (s1 < mv[q0]) { mv[q0] = s1; mi[q0] = n0 + 1; }
            if (s2 < mv[q1]) { mv[q1] = s2; mi[q1] = n0; }
            if (s3 < mv[q1]) { mv[q1] = s3; mi[q1] = n0 + 1; }
        }
#pragma unroll
    for (int o = 1; o < 4; o <<= 1)
#pragma unroll
        for (int q = 0; q < 4; q++) {
            float ov = __shfl_xor_sync(0xffffffffu, mv[q], o);
            int   oi = __shfl_xor_sync(0xffffffffu, mi[q], o);
            if (ov < mv[q] || (ov == mv[q] && oi < mi[q])) { mv[q] = ov; mi[q] = oi; }
        }
    if ((lane & 3) == 0) {
#pragma unroll
        for (int q = 0; q < 4; q++) {
            int r = wm * 32 + (q >> 1) * 16 + (lane >> 2) + (q & 1) * 8;
            bvs[r * 4 + wn] = mv[q];
            bis[r * 4 + wn] = mi[q];
        }
    }
    __syncthreads();
    if (tid < BM) {
        float bv = bvs[tid * 4]; int bi = bis[tid * 4];
#pragma unroll
        for (int w = 1; w < 4; w++) {
            float v = bvs[tid * 4 + w]; int i = bis[tid * 4 + w];
            if (v < bv || (v == bv && i < bi)) { bv = v; bi = i; }
        }
        rminv[tid] = bv;
        idx_s[tid] = bi;
    }
    __syncthreads();
    // candidate scan: any score within MARGIN of the row min
#pragma unroll
    for (int mt = 0; mt < 2; mt++) {
        int rA = wm * 32 + mt * 16 + (lane >> 2);
        float thA = rminv[rA] + MARGIN;
        float thB = rminv[rA + 8] + MARGIN;
#pragma unroll
        for (int nt = 0; nt < 8; nt++) {
            int n0 = wn * 64 + nt * 8 + (lane & 3) * 2;
            float cq0 = csq[n0], cq1 = csq[n0 + 1];
            float s0 = cq0 - 2.f * acc[mt][nt][0];
            float s1 = cq1 - 2.f * acc[mt][nt][1];
            float s2 = cq0 - 2.f * acc[mt][nt][2];
            float s3 = cq1 - 2.f * acc[mt][nt][3];
            if (s0 <= thA) { int p = atomicAdd(&cnt_s[rA], 1);     if (p < 8) cand[rA * 8 + p] = n0; }
            if (s1 <= thA) { int p = atomicAdd(&cnt_s[rA], 1);     if (p < 8) cand[rA * 8 + p] = n0 + 1; }
            if (s2 <= thB) { int p = atomicAdd(&cnt_s[rA + 8], 1); if (p < 8) cand[(rA + 8) * 8 + p] = n0; }
            if (s3 <= thB) { int p = atomicAdd(&cnt_s[rA + 8], 1); if (p < 8) cand[(rA + 8) * 8 + p] = n0 + 1; }
        }
    }
    __syncthreads();
    if (tid < BM && cnt_s[tid] > 1) {       // ambiguous under fast-path noise -> exact fixup
        int gi = atomicAdd(&g_nflag, 1);
        g_frow[gi] = rowBase + tid;
        int cc = cnt_s[tid] <= 8 ? cnt_s[tid] : 0;   // 0 => recompute all 256
        g_fcnt[gi] = cc;
        for (int j = 0; j < cc; j++) g_fcand[gi][j] = cand[tid * 8 + j];
    }

    // fused masked gather writeback (provisional for flagged rows)
    for (int i = tid; i < BM * (Hh / 4); i += NT) {
        int row = i >> 8;
        int u   = i & 255;
        int ci  = idx_s[row];
        float4 v = *reinterpret_cast<const float4*>(cb + (size_t)ci * Hh + u * 4);
        float m = (csq[ci] > 0.01f) ? 1.0f : 0.0f;
        v.x *= m; v.y *= m; v.z *= m; v.w *= m;
        *reinterpret_cast<float4*>(out + (size_t)(rowBase + row) * Hh + u * 4) = v;
    }
}

// ---------------- Kernel 3: exact fp32 fixup for flagged rows --------------
__global__ void fixup_kernel(const float* __restrict__ keys, const float* __restrict__ values,
                             const float* __restrict__ cb, float* __restrict__ out) {
    const int nflag = g_nflag;
    const int lane  = threadIdx.x & 31;
    const int warp  = (blockIdx.x * blockDim.x + threadIdx.x) >> 5;
    const int nwarp = (gridDim.x * blockDim.x) >> 5;

    for (int e = warp; e < nflag; e += nwarp) {
        int row = g_frow[e];
        int cc  = g_fcnt[e];
        const float4* xr = reinterpret_cast<const float4*>(
            row < ROWS_PER_TENSOR ? keys + (size_t)row * Hh
                                  : values + (size_t)(row - ROWS_PER_TENSOR) * Hh);
        int ncand = (cc == 0) ? Cc : cc;
        float bv = __int_as_float(0x7f800000);
        int   bi = 0x7fffffff;
        for (int j = 0; j < ncand; j++) {
            int c = (cc == 0) ? j : g_fcand[e][j];
            const float4* cr = reinterpret_cast<const float4*>(cb + (size_t)c * Hh);
            float d = 0.f;
#pragma unroll
            for (int t = 0; t < 8; t++) {
                float4 a = xr[lane + 32 * t];
                float4 b = cr[lane + 32 * t];
                d += a.x * b.x + a.y * b.y + a.z * b.z + a.w * b.w;
            }
#pragma unroll
            for (int o = 16; o > 0; o >>= 1) d += __shfl_xor_sync(0xffffffffu, d, o);
            float sc = g_csq[c] - 2.f * d;
            if (sc < bv || (sc == bv && c < bi)) { bv = sc; bi = c; }
        }
        float m = (g_csq[bi] > 0.01f) ? 1.0f : 0.0f;
        const float4* cr = reinterpret_cast<const float4*>(cb + (size_t)bi * Hh);
        float4* orow = reinterpret_cast<float4*>(out + (size_t)row * Hh);
#pragma unroll
        for (int t = 0; t < 8; t++) {
            float4 v = cr[lane + 32 * t];
            v.x *= m; v.y *= m; v.z *= m; v.w *= m;
            orow[lane + 32 * t] = v;
        }
    }
}

extern "C" void kernel_launch(void* const* d_in, const int* in_sizes, int n_in,
                              void* d_out, int out_size) {
    const float* keys     = (const float*)d_in[0];
    const float* values   = (const float*)d_in[1];
    const float* codebook = (const float*)d_in[2];
    float* out = (float*)d_out;

    cudaFuncSetAttribute(vq_gemm, cudaFuncAttributeMaxDynamicSharedMemorySize, SMEM_TOTAL);
    prep_kernel<<<Cc, 256>>>(codebook);
    vq_gemm<<<ROWS_TOTAL / BM, NT, SMEM_TOTAL>>>(keys, values, codebook, out);
    fixup_kernel<<<148, 256>>>(keys, values, codebook, out);
}

// round 4
// speedup vs baseline: 5.2289x; 1.8174x over previous
#include <cuda_runtime.h>
#include <cuda_bf16.h>
#include <cstdint>

// Problem constants (fixed): B=4, S=4096, H=1024, C=256
#define Hh 1024
#define Cc 256
#define ROWS_PER_TENSOR 16384
#define ROWS_TOTAL      32768
#define BM 128
#define KC 64
#define NCHUNK 16
#define NT 512
#define MARGIN 2.5f          // >= 2 * max plausible bf16 score error (rms ~0.1)

// __device__ scratch (no allocation allowed)
__device__ __nv_bfloat16 g_chi[Cc * Hh];
__device__ float g_csq[Cc];
__device__ int   g_nflag;
__device__ int   g_frow[ROWS_TOTAL];
__device__ int   g_fcnt[ROWS_TOTAL];
__device__ int   g_fcand[ROWS_TOTAL][8];

// ---------------- helpers ----------------
__device__ __forceinline__ uint32_t swz128(uint32_t off) {   // XOR bits[6:4] ^= bits[9:7]
    return off ^ ((off >> 3) & 0x70u);
}
__device__ __forceinline__ uint32_t smem_u32(const void* p) {
    uint32_t a;
    asm("{ .reg .u64 t; cvta.to.shared.u64 t, %1; cvt.u32.u64 %0, t; }" : "=r"(a) : "l"(p));
    return a;
}
__device__ __forceinline__ void cpa16(uint32_t dst, const void* src) {
    asm volatile("{ .reg .u64 g; cvta.to.global.u64 g, %1; "
                 "cp.async.cg.shared.global [%0], [g], 16; }"
                 :: "r"(dst), "l"(src) : "memory");
}
#define CP_COMMIT() asm volatile("cp.async.commit_group;" ::: "memory")
#define CP_WAIT0()  asm volatile("cp.async.wait_group 0;" ::: "memory")

__device__ __forceinline__ void ldsm4(uint32_t* r, uint32_t addr) {
    asm volatile("ldmatrix.sync.aligned.m8n8.x4.shared.b16 {%0,%1,%2,%3}, [%4];"
                 : "=r"(r[0]), "=r"(r[1]), "=r"(r[2]), "=r"(r[3]) : "r"(addr));
}
__device__ __forceinline__ void mma16816(float* d, const uint32_t* a, uint32_t b0, uint32_t b1) {
    asm volatile("mma.sync.aligned.m16n8k16.row.col.f32.bf16.bf16.f32 "
                 "{%0,%1,%2,%3}, {%4,%5,%6,%7}, {%8,%9}, {%0,%1,%2,%3};"
                 : "+f"(d[0]), "+f"(d[1]), "+f"(d[2]), "+f"(d[3])
                 : "r"(a[0]), "r"(a[1]), "r"(a[2]), "r"(a[3]), "r"(b0), "r"(b1));
}
// fp32x4 -> packed bf16 (RNE)
__device__ __forceinline__ void cvt4(const float4 v, uint32_t& h01, uint32_t& h23) {
    asm("cvt.rn.bf16x2.f32 %0, %1, %2;" : "=r"(h01) : "f"(v.y), "f"(v.x));
    asm("cvt.rn.bf16x2.f32 %0, %1, %2;" : "=r"(h23) : "f"(v.w), "f"(v.z));
}

// ---------------- Kernel 1: codebook bf16 + norms + flag reset -------------
__global__ void prep_kernel(const float* __restrict__ cb) {
    const int c = blockIdx.x;
    const int t = threadIdx.x;                 // 256 threads, one float4 each
    if (c == 0 && t == 0) g_nflag = 0;
    float4 v = reinterpret_cast<const float4*>(cb + (size_t)c * Hh)[t];
    float s = v.x * v.x + v.y * v.y + v.z * v.z + v.w * v.w;
    uint32_t h01, h23;
    cvt4(v, h01, h23);
    reinterpret_cast<uint2*>(g_chi + (size_t)c * Hh)[t] = make_uint2(h01, h23);
#pragma unroll
    for (int o = 16; o > 0; o >>= 1) s += __shfl_xor_sync(0xffffffffu, s, o);
    __shared__ float ws[8];
    if ((t & 31) == 0) ws[t >> 5] = s;
    __syncthreads();
    if (t == 0) {
        float tot = 0.f;
#pragma unroll
        for (int i = 0; i < 8; i++) tot += ws[i];
        g_csq[c] = tot;
    }
}

// ---------------- Kernel 2: mma.sync GEMM + argmin + gather ----------------
// smem: 2 stages x (A 16K | B 32K) + epilogue arrays
#define STG 49152
#define OFF_A(s) ((s) * STG + 0)
#define OFF_B(s) ((s) * STG + 16384)
#define OFF_CSQ   98304
#define OFF_BV    99328
#define OFF_BI   101376
#define OFF_RMIN 103424
#define OFF_IDX  103936
#define OFF_CNT  104448
#define OFF_CAND 104960
#define SMEM_TOTAL 109056

__global__ __launch_bounds__(NT, 1)
void vq_gemm(const float* __restrict__ keys, const float* __restrict__ values,
             const float* __restrict__ cb, float* __restrict__ out) {
    extern __shared__ __align__(1024) char smem[];
    const uint32_t sb = smem_u32(smem);
    const int tid  = threadIdx.x;
    const int lane = tid & 31;
    const int wid  = tid >> 5;
    const int wm   = wid >> 2;          // 0..3 (M)
    const int wn   = wid & 3;           // 0..3 (N)
    const int rowBase = blockIdx.x * BM;

    const float* src_base; int srcRow;
    if (rowBase < ROWS_PER_TENSOR) { src_base = keys;   srcRow = rowBase; }
    else                           { src_base = values; srcRow = rowBase - ROWS_PER_TENSOR; }

    if (tid < Cc) reinterpret_cast<float*>(smem + OFF_CSQ)[tid] = g_csq[tid];
    if (tid < BM) reinterpret_cast<int*>(smem + OFF_CNT)[tid] = 0;

    float acc[2][8][4];
#pragma unroll
    for (int a = 0; a < 2; a++)
#pragma unroll
        for (int b = 0; b < 8; b++)
#pragma unroll
            for (int k = 0; k < 4; k++) acc[a][b][k] = 0.f;

    auto loadB = [&](int c, int s) {
#pragma unroll
        for (int i = 0; i < 4; i++) {
            int li = tid + i * NT;
            int row = li >> 3, u = li & 7;
            const __nv_bfloat16* gh = g_chi + (size_t)row * Hh + c * KC + u * 8;
            uint32_t off = swz128((uint32_t)(row * 128 + u * 16));
            cpa16(sb + OFF_B(s) + off, gh);
        }
    };
    auto loadA = [&](float4* pf, int c) {
#pragma unroll
        for (int i = 0; i < 4; i++) {
            int li = tid + i * NT;
            int row = li >> 4, u = li & 15;
            pf[i] = *reinterpret_cast<const float4*>(
                src_base + (size_t)(srcRow + row) * Hh + c * KC + u * 4);
        }
    };
    auto storeA = [&](const float4* pf, int s) {
#pragma unroll
        for (int i = 0; i < 4; i++) {
            int li = tid + i * NT;
            int row = li >> 4, u = li & 15;
            uint32_t h01, h23;
            cvt4(pf[i], h01, h23);
            uint32_t off = swz128((uint32_t)(row * 128 + u * 8));
            *reinterpret_cast<uint2*>(smem + OFF_A(s) + off) = make_uint2(h01, h23);
        }
    };

    const int aRowB = (wm * 32 + (lane & 15)) * 128;
    const int aColB = (lane >> 4) * 16;
    const int bRow  = wn * 64 + ((lane >> 4) << 3) + (lane & 7);  // + p*16
    const int bColB = ((lane >> 3) & 1) * 16;

    float4 pf[4];
    loadB(0, 0); CP_COMMIT();
    loadA(pf, 0);
    storeA(pf, 0);
    CP_WAIT0();
    __syncthreads();

    for (int c = 0; c < NCHUNK; c++) {
        const int s = c & 1;
        if (c + 1 < NCHUNK) { loadB(c + 1, s ^ 1); CP_COMMIT(); loadA(pf, c + 1); }

        const uint32_t aS = sb + OFF_A(s), bS = sb + OFF_B(s);
#pragma unroll
        for (int ks = 0; ks < 4; ks++) {
            uint32_t ah[2][4];
#pragma unroll
            for (int mt = 0; mt < 2; mt++)
                ldsm4(ah[mt], aS + swz128((uint32_t)(aRowB + mt * 2048 + ks * 32 + aColB)));
#pragma unroll
            for (int p = 0; p < 4; p++) {
                uint32_t bh[4];
                ldsm4(bh, bS + swz128((uint32_t)((bRow + p * 16) * 128 + ks * 32 + bColB)));
#pragma unroll
                for (int mt = 0; mt < 2; mt++) {
                    mma16816(acc[mt][2 * p],     ah[mt], bh[0], bh[1]);
                    mma16816(acc[mt][2 * p + 1], ah[mt], bh[2], bh[3]);
                }
            }
        }
        if (c + 1 < NCHUNK) { storeA(pf, s ^ 1); CP_WAIT0(); }
        __syncthreads();
    }

    // ---- epilogue: scores, per-row argmin, candidates, writeback ----
    const float* csq = reinterpret_cast<const float*>(smem + OFF_CSQ);
    float* bvs   = reinterpret_cast<float*>(smem + OFF_BV);
    int*   bis   = reinterpret_cast<int*>(smem + OFF_BI);
    float* rminv = reinterpret_cast<float*>(smem + OFF_RMIN);
    int*   idx_s = reinterpret_cast<int*>(smem + OFF_IDX);
    int*   cnt_s = reinterpret_cast<int*>(smem + OFF_CNT);
    int*   cand  = reinterpret_cast<int*>(smem + OFF_CAND);

    float mv[4]; int mi[4];
#pragma unroll
    for (int q = 0; q < 4; q++) { mv[q] = __int_as_float(0x7f800000); mi[q] = 0x7fffffff; }
#pragma unroll
    for (int mt = 0; mt < 2; mt++)
#pragma unroll
        for (int nt = 0; nt < 8; nt++) {
            int n0 = wn * 64 + nt * 8 + (lane & 3) * 2;
            float cq0 = csq[n0], cq1 = csq[n0 + 1];
            float s0 = cq0 - 2.f * acc[mt][nt][0];
            float s1 = cq1 - 2.f * acc[mt][nt][1];
            float s2 = cq0 - 2.f * acc[mt][nt][2];
            float s3 = cq1 - 2.f * acc[mt][nt][3];
            int q0 = mt * 2, q1 = mt * 2 + 1;
            if (s0 < mv[q0]) { mv[q0] = s0; mi[q0] = n0; }
            if (s1 < mv[q0]) { mv[q0] = s1; mi[q0] = n0 + 1; }
            if (s2 < mv[q1]) { mv[q1] = s2; mi[q1] = n0; }
            if (s3 < mv[q1]) { mv[q1] = s3; mi[q1] = n0 + 1; }
        }
#pragma unroll
    for (int o = 1; o < 4; o <<= 1)
#pragma unroll
        for (int q = 0; q < 4; q++) {
            float ov = __shfl_xor_sync(0xffffffffu, mv[q], o);
            int   oi = __shfl_xor_sync(0xffffffffu, mi[q], o);
            if (ov < mv[q] || (ov == mv[q] && oi < mi[q])) { mv[q] = ov; mi[q] = oi; }
        }
    if ((lane & 3) == 0) {
#pragma unroll
        for (int q = 0; q < 4; q++) {
            int r = wm * 32 + (q >> 1) * 16 + (lane >> 2) + (q & 1) * 8;
            bvs[r * 4 + wn] = mv[q];
            bis[r * 4 + wn] = mi[q];
        }
    }
    __syncthreads();
    if (tid < BM) {
        float bv = bvs[tid * 4]; int bi = bis[tid * 4];
#pragma unroll
        for (int w = 1; w < 4; w++) {
            float v = bvs[tid * 4 + w]; int i = bis[tid * 4 + w];
            if (v < bv || (v == bv && i < bi)) { bv = v; bi = i; }
        }
        rminv[tid] = bv;
        idx_s[tid] = bi;
    }
    __syncthreads();
    // candidate scan: any score within MARGIN of the row min -> exact recheck
#pragma unroll
    for (int mt = 0; mt < 2; mt++) {
        int rA = wm * 32 + mt * 16 + (lane >> 2);
        float thA = rminv[rA] + MARGIN;
        float thB = rminv[rA + 8] + MARGIN;
#pragma unroll
        for (int nt = 0; nt < 8; nt++) {
            int n0 = wn * 64 + nt * 8 + (lane & 3) * 2;
            float cq0 = csq[n0], cq1 = csq[n0 + 1];
            float s0 = cq0 - 2.f * acc[mt][nt][0];
            float s1 = cq1 - 2.f * acc[mt][nt][1];
            float s2 = cq0 - 2.f * acc[mt][nt][2];
            float s3 = cq1 - 2.f * acc[mt][nt][3];
            if (s0 <= thA) { int p = atomicAdd(&cnt_s[rA], 1);     if (p < 8) cand[rA * 8 + p] = n0; }
            if (s1 <= thA) { int p = atomicAdd(&cnt_s[rA], 1);     if (p < 8) cand[rA * 8 + p] = n0 + 1; }
            if (s2 <= thB) { int p = atomicAdd(&cnt_s[rA + 8], 1); if (p < 8) cand[(rA + 8) * 8 + p] = n0; }
            if (s3 <= thB) { int p = atomicAdd(&cnt_s[rA + 8], 1); if (p < 8) cand[(rA + 8) * 8 + p] = n0 + 1; }
        }
    }
    __syncthreads();
    if (tid < BM && cnt_s[tid] > 1) {       // ambiguous under bf16 noise -> exact fixup
        int gi = atomicAdd(&g_nflag, 1);
        g_frow[gi] = rowBase + tid;
        int cc = cnt_s[tid] <= 8 ? cnt_s[tid] : 0;   // 0 => recompute all 256
        g_fcnt[gi] = cc;
        for (int j = 0; j < cc; j++) g_fcand[gi][j] = cand[tid * 8 + j];
    }

    // fused masked gather writeback (provisional for flagged rows)
    for (int i = tid; i < BM * (Hh / 4); i += NT) {
        int row = i >> 8;
        int u   = i & 255;
        int ci  = idx_s[row];
        float4 v = *reinterpret_cast<const float4*>(cb + (size_t)ci * Hh + u * 4);
        float m = (csq[ci] > 0.01f) ? 1.0f : 0.0f;
        v.x *= m; v.y *= m; v.z *= m; v.w *= m;
        *reinterpret_cast<float4*>(out + (size_t)(rowBase + row) * Hh + u * 4) = v;
    }
}

// ---------------- Kernel 3: exact fp32 fixup for flagged rows --------------
__global__ void fixup_kernel(const float* __restrict__ keys, const float* __restrict__ values,
                             const float* __restrict__ cb, float* __restrict__ out) {
    const int nflag = g_nflag;
    const int lane  = threadIdx.x & 31;
    const int warp  = (blockIdx.x * blockDim.x + threadIdx.x) >> 5;
    const int nwarp = (gridDim.x * blockDim.x) >> 5;

    for (int e = warp; e < nflag; e += nwarp) {
        int row = g_frow[e];
        int cc  = g_fcnt[e];
        const float4* xr = reinterpret_cast<const float4*>(
            row < ROWS_PER_TENSOR ? keys + (size_t)row * Hh
                                  : values + (size_t)(row - ROWS_PER_TENSOR) * Hh);
        float4 xa[8];
#pragma unroll
        for (int t = 0; t < 8; t++) xa[t] = xr[lane + 32 * t];
        int ncand = (cc == 0) ? Cc : cc;
        float bv = __int_as_float(0x7f800000);
        int   bi = 0x7fffffff;
        for (int j = 0; j < ncand; j++) {
            int c = (cc == 0) ? j : g_fcand[e][j];
            const float4* cr = reinterpret_cast<const float4*>(cb + (size_t)c * Hh);
            float d = 0.f;
#pragma unroll
            for (int t = 0; t < 8; t++) {
                float4 b = cr[lane + 32 * t];
                d += xa[t].x * b.x + xa[t].y * b.y + xa[t].z * b.z + xa[t].w * b.w;
            }
#pragma unroll
            for (int o = 16; o > 0; o >>= 1) d += __shfl_xor_sync(0xffffffffu, d, o);
            float sc = g_csq[c] - 2.f * d;
            if (sc < bv || (sc == bv && c < bi)) { bv = sc; bi = c; }
        }
        float m = (g_csq[bi] > 0.01f) ? 1.0f : 0.0f;
        const float4* cr = reinterpret_cast<const float4*>(cb + (size_t)bi * Hh);
        float4* orow = reinterpret_cast<float4*>(out + (size_t)row * Hh);
#pragma unroll
        for (int t = 0; t < 8; t++) {
            float4 v = cr[lane + 32 * t];
            v.x *= m; v.y *= m; v.z *= m; v.w *= m;
            orow[lane + 32 * t] = v;
        }
    }
}

extern "C" void kernel_launch(void* const* d_in, const int* in_sizes, int n_in,
                              void* d_out, int out_size) {
    const float* keys     = (const float*)d_in[0];
    const float* values   = (const float*)d_in[1];
    const float* codebook = (const float*)d_in[2];
    float* out = (float*)d_out;

    cudaFuncSetAttribute(vq_gemm, cudaFuncAttributeMaxDynamicSharedMemorySize, SMEM_TOTAL);
    prep_kernel<<<Cc, 256>>>(codebook);
    vq_gemm<<<ROWS_TOTAL / BM, NT, SMEM_TOTAL>>>(keys, values, codebook, out);
    fixup_kernel<<<148, 256>>>(keys, values, codebook, out);
}

// round 5
// speedup vs baseline: 5.4542x; 1.0431x over previous
#include <cuda_runtime.h>
#include <cuda_bf16.h>
#include <cstdint>

// Problem constants (fixed): B=4, S=4096, H=1024, C=256
#define Hh 1024
#define Cc 256
#define ROWS_PER_TENSOR 16384
#define ROWS_TOTAL      32768
#define BM 64
#define KC 64
#define NCHUNK 16
#define NT 256
#define MARGIN 2.5f          // >= 2 * max plausible bf16 score error (rms ~0.1)

// __device__ scratch (no allocation allowed)
__device__ __nv_bfloat16 g_chi[Cc * Hh];
__device__ float g_csq[Cc];
__device__ int   g_nflag;
__device__ int   g_frow[ROWS_TOTAL];
__device__ int   g_fcnt[ROWS_TOTAL];
__device__ int   g_fcand[ROWS_TOTAL][8];

// ---------------- helpers ----------------
__device__ __forceinline__ uint32_t swz128(uint32_t off) {   // XOR bits[6:4] ^= bits[9:7]
    return off ^ ((off >> 3) & 0x70u);
}
__device__ __forceinline__ uint32_t smem_u32(const void* p) {
    uint32_t a;
    asm("{ .reg .u64 t; cvta.to.shared.u64 t, %1; cvt.u32.u64 %0, t; }" : "=r"(a) : "l"(p));
    return a;
}
__device__ __forceinline__ void cpa16(uint32_t dst, const void* src) {
    asm volatile("{ .reg .u64 g; cvta.to.global.u64 g, %1; "
                 "cp.async.cg.shared.global [%0], [g], 16; }"
                 :: "r"(dst), "l"(src) : "memory");
}
#define CP_COMMIT() asm volatile("cp.async.commit_group;" ::: "memory")
#define CP_WAIT0()  asm volatile("cp.async.wait_group 0;" ::: "memory")

__device__ __forceinline__ void ldsm4(uint32_t* r, uint32_t addr) {
    asm volatile("ldmatrix.sync.aligned.m8n8.x4.shared.b16 {%0,%1,%2,%3}, [%4];"
                 : "=r"(r[0]), "=r"(r[1]), "=r"(r[2]), "=r"(r[3]) : "r"(addr));
}
__device__ __forceinline__ void mma16816(float* d, const uint32_t* a, uint32_t b0, uint32_t b1) {
    asm volatile("mma.sync.aligned.m16n8k16.row.col.f32.bf16.bf16.f32 "
                 "{%0,%1,%2,%3}, {%4,%5,%6,%7}, {%8,%9}, {%0,%1,%2,%3};"
                 : "+f"(d[0]), "+f"(d[1]), "+f"(d[2]), "+f"(d[3])
                 : "r"(a[0]), "r"(a[1]), "r"(a[2]), "r"(a[3]), "r"(b0), "r"(b1));
}
// fp32x4 -> packed bf16 (RNE)
__device__ __forceinline__ void cvt4(const float4 v, uint32_t& h01, uint32_t& h23) {
    asm("cvt.rn.bf16x2.f32 %0, %1, %2;" : "=r"(h01) : "f"(v.y), "f"(v.x));
    asm("cvt.rn.bf16x2.f32 %0, %1, %2;" : "=r"(h23) : "f"(v.w), "f"(v.z));
}

// ---------------- Kernel 1: codebook bf16 + norms + flag reset -------------
__global__ void prep_kernel(const float* __restrict__ cb) {
    const int c = blockIdx.x;
    const int t = threadIdx.x;                 // 256 threads, one float4 each
    if (c == 0 && t == 0) g_nflag = 0;
    float4 v = reinterpret_cast<const float4*>(cb + (size_t)c * Hh)[t];
    float s = v.x * v.x + v.y * v.y + v.z * v.z + v.w * v.w;
    uint32_t h01, h23;
    cvt4(v, h01, h23);
    reinterpret_cast<uint2*>(g_chi + (size_t)c * Hh)[t] = make_uint2(h01, h23);
#pragma unroll
    for (int o = 16; o > 0; o >>= 1) s += __shfl_xor_sync(0xffffffffu, s, o);
    __shared__ float ws[8];
    if ((t & 31) == 0) ws[t >> 5] = s;
    __syncthreads();
    if (t == 0) {
        float tot = 0.f;
#pragma unroll
        for (int i = 0; i < 8; i++) tot += ws[i];
        g_csq[c] = tot;
    }
}

// ---------------- Kernel 2: mma.sync GEMM + argmin + gather ----------------
// smem per stage: A 64x64 bf16 = 8K | B 256x64 bf16 = 32K
#define STG 40960
#define OFF_A(s) ((s) * STG + 0)
#define OFF_B(s) ((s) * STG + 8192)
#define OFF_CSQ   81920
#define OFF_BV    82944
#define OFF_BI    83968
#define OFF_RMIN  84992
#define OFF_IDX   85248
#define OFF_CNT   85504
#define OFF_CAND  85760
#define SMEM_TOTAL 87808

__global__ __launch_bounds__(NT, 2)
void vq_gemm(const float* __restrict__ keys, const float* __restrict__ values,
             const float* __restrict__ cb, float* __restrict__ out) {
    extern __shared__ __align__(1024) char smem[];
    const uint32_t sb = smem_u32(smem);
    const int tid  = threadIdx.x;
    const int lane = tid & 31;
    const int wid  = tid >> 5;          // 0..7
    const int wm   = wid >> 2;          // 0..1 (M)
    const int wn   = wid & 3;           // 0..3 (N)
    const int rowBase = blockIdx.x * BM;

    const float* src_base; int srcRow;
    if (rowBase < ROWS_PER_TENSOR) { src_base = keys;   srcRow = rowBase; }
    else                           { src_base = values; srcRow = rowBase - ROWS_PER_TENSOR; }

    if (tid < Cc) reinterpret_cast<float*>(smem + OFF_CSQ)[tid] = g_csq[tid];
    if (tid < BM) reinterpret_cast<int*>(smem + OFF_CNT)[tid] = 0;

    float acc[2][8][4];
#pragma unroll
    for (int a = 0; a < 2; a++)
#pragma unroll
        for (int b = 0; b < 8; b++)
#pragma unroll
            for (int k = 0; k < 4; k++) acc[a][b][k] = 0.f;

    auto loadB = [&](int c, int s) {     // 256x64 bf16 = 2048 16B units, 8 per thread
#pragma unroll
        for (int i = 0; i < 8; i++) {
            int li = tid + i * NT;
            int row = li >> 3, u = li & 7;
            const __nv_bfloat16* gh = g_chi + (size_t)row * Hh + c * KC + u * 8;
            uint32_t off = swz128((uint32_t)(row * 128 + u * 16));
            cpa16(sb + OFF_B(s) + off, gh);
        }
    };
    auto loadA = [&](float4* pf, int c) {  // 64x64 fp32 = 1024 float4, 4 per thread
#pragma unroll
        for (int i = 0; i < 4; i++) {
            int li = tid + i * NT;
            int row = li >> 4, u = li & 15;
            pf[i] = *reinterpret_cast<const float4*>(
                src_base + (size_t)(srcRow + row) * Hh + c * KC + u * 4);
        }
    };
    auto storeA = [&](const float4* pf, int s) {
#pragma unroll
        for (int i = 0; i < 4; i++) {
            int li = tid + i * NT;
            int row = li >> 4, u = li & 15;
            uint32_t h01, h23;
            cvt4(pf[i], h01, h23);
            uint32_t off = swz128((uint32_t)(row * 128 + u * 8));
            *reinterpret_cast<uint2*>(smem + OFF_A(s) + off) = make_uint2(h01, h23);
        }
    };

    const int aRowB = (wm * 32 + (lane & 15)) * 128;              // + mt*2048
    const int aColB = (lane >> 4) * 16;
    const int bRow  = wn * 64 + ((lane >> 4) << 3) + (lane & 7);  // + p*16
    const int bColB = ((lane >> 3) & 1) * 16;

    float4 pf[4];
    loadB(0, 0); CP_COMMIT();
    loadA(pf, 0);
    storeA(pf, 0);
    CP_WAIT0();
    __syncthreads();

    for (int c = 0; c < NCHUNK; c++) {
        const int s = c & 1;
        if (c + 1 < NCHUNK) { loadB(c + 1, s ^ 1); CP_COMMIT(); loadA(pf, c + 1); }

        const uint32_t aS = sb + OFF_A(s), bS = sb + OFF_B(s);
#pragma unroll
        for (int ks = 0; ks < 4; ks++) {
            uint32_t ah[2][4];
#pragma unroll
            for (int mt = 0; mt < 2; mt++)
                ldsm4(ah[mt], aS + swz128((uint32_t)(aRowB + mt * 2048 + ks * 32 + aColB)));
#pragma unroll
            for (int p = 0; p < 4; p++) {
                uint32_t bh[4];
                ldsm4(bh, bS + swz128((uint32_t)((bRow + p * 16) * 128 + ks * 32 + bColB)));
#pragma unroll
                for (int mt = 0; mt < 2; mt++) {
                    mma16816(acc[mt][2 * p],     ah[mt], bh[0], bh[1]);
                    mma16816(acc[mt][2 * p + 1], ah[mt], bh[2], bh[3]);
                }
            }
        }
        if (c + 1 < NCHUNK) { storeA(pf, s ^ 1); CP_WAIT0(); }
        __syncthreads();
    }

    // ---- epilogue: scores, per-row argmin, candidates, writeback ----
    const float* csq = reinterpret_cast<const float*>(smem + OFF_CSQ);
    float* bvs   = reinterpret_cast<float*>(smem + OFF_BV);
    int*   bis   = reinterpret_cast<int*>(smem + OFF_BI);
    float* rminv = reinterpret_cast<float*>(smem + OFF_RMIN);
    int*   idx_s = reinterpret_cast<int*>(smem + OFF_IDX);
    int*   cnt_s = reinterpret_cast<int*>(smem + OFF_CNT);
    int*   cand  = reinterpret_cast<int*>(smem + OFF_CAND);

    float mv[4]; int mi[4];
#pragma unroll
    for (int q = 0; q < 4; q++) { mv[q] = __int_as_float(0x7f800000); mi[q] = 0x7fffffff; }
#pragma unroll
    for (int mt = 0; mt < 2; mt++)
#pragma unroll
        for (int nt = 0; nt < 8; nt++) {
            int n0 = wn * 64 + nt * 8 + (lane & 3) * 2;
            float cq0 = csq[n0], cq1 = csq[n0 + 1];
            float s0 = cq0 - 2.f * acc[mt][nt][0];
            float s1 = cq1 - 2.f * acc[mt][nt][1];
            float s2 = cq0 - 2.f * acc[mt][nt][2];
            float s3 = cq1 - 2.f * acc[mt][nt][3];
            int q0 = mt * 2, q1 = mt * 2 + 1;
            if (s0 < mv[q0]) { mv[q0] = s0; mi[q0] = n0; }
            if (s1 < mv[q0]) { mv[q0] = s1; mi[q0] = n0 + 1; }
            if (s2 < mv[q1]) { mv[q1] = s2; mi[q1] = n0; }
            if (s3 < mv[q1]) { mv[q1] = s3; mi[q1] = n0 + 1; }
        }
#pragma unroll
    for (int o = 1; o < 4; o <<= 1)
#pragma unroll
        for (int q = 0; q < 4; q++) {
            float ov = __shfl_xor_sync(0xffffffffu, mv[q], o);
            int   oi = __shfl_xor_sync(0xffffffffu, mi[q], o);
            if (ov < mv[q] || (ov == mv[q] && oi < mi[q])) { mv[q] = ov; mi[q] = oi; }
        }
    if ((lane & 3) == 0) {
#pragma unroll
        for (int q = 0; q < 4; q++) {
            int r = wm * 32 + (q >> 1) * 16 + (lane >> 2) + (q & 1) * 8;
            bvs[r * 4 + wn] = mv[q];
            bis[r * 4 + wn] = mi[q];
        }
    }
    __syncthreads();
    if (tid < BM) {
        float bv = bvs[tid * 4]; int bi = bis[tid * 4];
#pragma unroll
        for (int w = 1; w < 4; w++) {
            float v = bvs[tid * 4 + w]; int i = bis[tid * 4 + w];
            if (v < bv || (v == bv && i < bi)) { bv = v; bi = i; }
        }
        rminv[tid] = bv;
        idx_s[tid] = bi;
    }
    __syncthreads();
    // candidate scan: any score within MARGIN of the row min -> exact recheck
#pragma unroll
    for (int mt = 0; mt < 2; mt++) {
        int rA = wm * 32 + mt * 16 + (lane >> 2);
        float thA = rminv[rA] + MARGIN;
        float thB = rminv[rA + 8] + MARGIN;
#pragma unroll
        for (int nt = 0; nt < 8; nt++) {
            int n0 = wn * 64 + nt * 8 + (lane & 3) * 2;
            float cq0 = csq[n0], cq1 = csq[n0 + 1];
            float s0 = cq0 - 2.f * acc[mt][nt][0];
            float s1 = cq1 - 2.f * acc[mt][nt][1];
            float s2 = cq0 - 2.f * acc[mt][nt][2];
            float s3 = cq1 - 2.f * acc[mt][nt][3];
            if (s0 <= thA) { int p = atomicAdd(&cnt_s[rA], 1);     if (p < 8) cand[rA * 8 + p] = n0; }
            if (s1 <= thA) { int p = atomicAdd(&cnt_s[rA], 1);     if (p < 8) cand[rA * 8 + p] = n0 + 1; }
            if (s2 <= thB) { int p = atomicAdd(&cnt_s[rA + 8], 1); if (p < 8) cand[(rA + 8) * 8 + p] = n0; }
            if (s3 <= thB) { int p = atomicAdd(&cnt_s[rA + 8], 1); if (p < 8) cand[(rA + 8) * 8 + p] = n0 + 1; }
        }
    }
    __syncthreads();
    if (tid < BM && cnt_s[tid] > 1) {       // ambiguous under bf16 noise -> exact fixup
        int gi = atomicAdd(&g_nflag, 1);
        g_frow[gi] = rowBase + tid;
        int cc = cnt_s[tid] <= 8 ? cnt_s[tid] : 0;   // 0 => recompute all 256
        g_fcnt[gi] = cc;
        for (int j = 0; j < cc; j++) g_fcand[gi][j] = cand[tid * 8 + j];
    }

    // fused masked gather writeback (streaming stores; provisional for flagged rows)
    for (int i = tid; i < BM * (Hh / 4); i += NT) {
        int row = i >> 8;
        int u   = i & 255;
        int ci  = idx_s[row];
        float4 v = *reinterpret_cast<const float4*>(cb + (size_t)ci * Hh + u * 4);
        float m = (csq[ci] > 0.01f) ? 1.0f : 0.0f;
        v.x *= m; v.y *= m; v.z *= m; v.w *= m;
        __stcs(reinterpret_cast<float4*>(out + (size_t)(rowBase + row) * Hh + u * 4), v);
    }
}

// ---------------- Kernel 3: exact fp32 fixup for flagged rows --------------
__global__ void fixup_kernel(const float* __restrict__ keys, const float* __restrict__ values,
                             const float* __restrict__ cb, float* __restrict__ out) {
    const int nflag = g_nflag;
    const int lane  = threadIdx.x & 31;
    const int warp  = (blockIdx.x * blockDim.x + threadIdx.x) >> 5;
    const int nwarp = (gridDim.x * blockDim.x) >> 5;

    for (int e = warp; e < nflag; e += nwarp) {
        int row = g_frow[e];
        int cc  = g_fcnt[e];
        const float4* xr = reinterpret_cast<const float4*>(
            row < ROWS_PER_TENSOR ? keys + (size_t)row * Hh
                                  : values + (size_t)(row - ROWS_PER_TENSOR) * Hh);
        float4 xa[8];
#pragma unroll
        for (int t = 0; t < 8; t++) xa[t] = xr[lane + 32 * t];
        int ncand = (cc == 0) ? Cc : cc;
        float bv = __int_as_float(0x7f800000);
        int   bi = 0x7fffffff;
        for (int j = 0; j < ncand; j++) {
            int c = (cc == 0) ? j : g_fcand[e][j];
            const float4* cr = reinterpret_cast<const float4*>(cb + (size_t)c * Hh);
            float d = 0.f;
#pragma unroll
            for (int t = 0; t < 8; t++) {
                float4 b = cr[lane + 32 * t];
                d += xa[t].x * b.x + xa[t].y * b.y + xa[t].z * b.z + xa[t].w * b.w;
            }
#pragma unroll
            for (int o = 16; o > 0; o >>= 1) d += __shfl_xor_sync(0xffffffffu, d, o);
            float sc = g_csq[c] - 2.f * d;
            if (sc < bv || (sc == bv && c < bi)) { bv = sc; bi = c; }
        }
        float m = (g_csq[bi] > 0.01f) ? 1.0f : 0.0f;
        const float4* cr = reinterpret_cast<const float4*>(cb + (size_t)bi * Hh);
        float4* orow = reinterpret_cast<float4*>(out + (size_t)row * Hh);
#pragma unroll
        for (int t = 0; t < 8; t++) {
            float4 v = cr[lane + 32 * t];
            v.x *= m; v.y *= m; v.z *= m; v.w *= m;
            orow[lane + 32 * t] = v;
        }
    }
}

extern "C" void kernel_launch(void* const* d_in, const int* in_sizes, int n_in,
                              void* d_out, int out_size) {
    const float* keys     = (const float*)d_in[0];
    const float* values   = (const float*)d_in[1];
    const float* codebook = (const float*)d_in[2];
    float* out = (float*)d_out;

    cudaFuncSetAttribute(vq_gemm, cudaFuncAttributeMaxDynamicSharedMemorySize, SMEM_TOTAL);
    prep_kernel<<<Cc, 256>>>(codebook);
    vq_gemm<<<ROWS_TOTAL / BM, NT, SMEM_TOTAL>>>(keys, values, codebook, out);
    fixup_kernel<<<148, 256>>>(keys, values, codebook, out);
}